// round 17
// baseline (speedup 1.0000x reference)
#include <cuda_runtime.h>
#include <cuda_bf16.h>
#include <math.h>
#include <stdint.h>

#define B_SZ     4
#define C_DIM    256
#define T_LEN    4096
#define FF_DIM   1024
#define NLAYERS  2
#define CHUNK    128
#define S_LEN    384
#define NW       32
#define NSEQ     128
#define M_TOTAL  49152
#define NHEADS   8
#define DH       32
#define EPS      1e-5f

typedef __nv_bfloat16  bf16;
typedef __nv_bfloat162 bf162;

__device__ float g_bufA [M_TOTAL * C_DIM];
__device__ float g_bufB [M_TOTAL * C_DIM];
__device__ float g_proj [M_TOTAL * C_DIM];
__device__ bf16  g_bufAh[M_TOTAL * C_DIM];
__device__ bf16  g_bufBh[M_TOTAL * C_DIM];
__device__ bf16  g_qkv  [M_TOTAL * 768];
__device__ bf16  g_att  [M_TOTAL * C_DIM];
__device__ bf16  g_h    [M_TOTAL * FF_DIM];
__device__ bf16  g_wbf  [2097152];

#define OFF_SAW   0
#define OFF_SAOW  393216
#define OFF_CAW   524288
#define OFF_CAOW  917504
#define OFF_W1    1048576
#define OFF_W2    1572864

__device__ __forceinline__ uint32_t packbf(float x, float y)
{
    bf162 h = __floats2bfloat162_rn(x, y);
    return *(uint32_t*)&h;
}

__device__ __forceinline__ float ex2f(float x)
{
    float r;
    asm("ex2.approx.ftz.f32 %0, %1;" : "=f"(r) : "f"(x));
    return r;
}

__device__ __forceinline__ void mma_bf16(float* c, const uint32_t* a, const uint32_t* b)
{
    asm volatile("mma.sync.aligned.m16n8k16.row.col.f32.bf16.bf16.f32 "
                 "{%0,%1,%2,%3}, {%4,%5,%6,%7}, {%8,%9}, {%0,%1,%2,%3};"
                 : "+f"(c[0]), "+f"(c[1]), "+f"(c[2]), "+f"(c[3])
                 : "r"(a[0]), "r"(a[1]), "r"(a[2]), "r"(a[3]),
                   "r"(b[0]), "r"(b[1]));
}

__device__ __forceinline__ void ldsm_x4b(uint32_t* d, const bf16* p)
{
    uint32_t a = (uint32_t)__cvta_generic_to_shared(p);
    asm volatile("ldmatrix.sync.aligned.m8n8.x4.shared.b16 {%0,%1,%2,%3}, [%4];"
                 : "=r"(d[0]), "=r"(d[1]), "=r"(d[2]), "=r"(d[3]) : "r"(a));
}

__device__ __forceinline__ void cp16(bf16* dst, const bf16* src)
{
    uint32_t d = (uint32_t)__cvta_generic_to_shared(dst);
    asm volatile("cp.async.ca.shared.global [%0], [%1], 16;" :: "r"(d), "l"(src));
}
#define CP_COMMIT() asm volatile("cp.async.commit_group;")
#define CP_WAIT2()  asm volatile("cp.async.wait_group 2;")

__global__ void convert_w_kernel(const float* __restrict__ src, bf16* __restrict__ dst, int n4)
{
    int i = blockIdx.x * blockDim.x + threadIdx.x;
    if (i < n4) {
        float4 v = ((const float4*)src)[i];
        bf162 a = __floats2bfloat162_rn(v.x, v.y);
        bf162 b = __floats2bfloat162_rn(v.z, v.w);
        ((bf162*)dst)[2 * i]     = a;
        ((bf162*)dst)[2 * i + 1] = b;
    }
}

__global__ void convert_w2_kernel(const float* __restrict__ s0, bf16* __restrict__ d0, int n40,
                                  const float* __restrict__ s1, bf16* __restrict__ d1, int n41)
{
    int i = blockIdx.x * blockDim.x + threadIdx.x;
    const float* src = blockIdx.y ? s1 : s0;
    bf16*        dst = blockIdx.y ? d1 : d0;
    int          n4  = blockIdx.y ? n41 : n40;
    if (i < n4) {
        float4 v = ((const float4*)src)[i];
        bf162 a = __floats2bfloat162_rn(v.x, v.y);
        bf162 b = __floats2bfloat162_rn(v.z, v.w);
        ((bf162*)dst)[2 * i]     = a;
        ((bf162*)dst)[2 * i + 1] = b;
    }
}

__global__ void build_x_kernel(const float* __restrict__ mem, float* __restrict__ x,
                               bf16* __restrict__ xh)
{
    __shared__ float tile[32][33];
    int p0 = blockIdx.x * 32, c0 = blockIdx.y * 32, seq = blockIdx.z;
    int b = seq >> 5, w = seq & 31;
    int tx = threadIdx.x, ty = threadIdx.y;
    int t_off = w * CHUNK + p0 - CHUNK;
    #pragma unroll
    for (int i = ty; i < 32; i += 8) {
        int tpos = t_off + tx;
        float v = 0.f;
        if (tpos >= 0 && tpos < T_LEN)
            v = mem[((size_t)b * C_DIM + c0 + i) * T_LEN + tpos];
        tile[i][tx] = v;
    }
    __syncthreads();
    #pragma unroll
    for (int i = ty; i < 32; i += 8) {
        int p = p0 + i;
        int c = c0 + tx;
        int j = c >> 1;
        float dv  = __expf((float)(2 * j) * (-9.210340371976184f / (float)C_DIM));
        float ang = (float)p * dv;
        float pe  = (c & 1) ? cosf(ang) : sinf(ang);
        float val = tile[tx][i] + pe;
        size_t idx = ((size_t)seq * S_LEN + p) * C_DIM + c;
        x[idx]  = val;
        xh[idx] = __float2bfloat16_rn(val);
    }
}

// ---------------------------------------------------------------------------
// bf16 GEMM, 4-stage cp.async pipeline, ONE sync per k-iter.
// ---------------------------------------------------------------------------
#define GSTR 40
#define GEMM_STAGE (128 * GSTR)
#define GEMM_SMEM_BYTES (8 * GEMM_STAGE * (int)sizeof(bf16))   // 81920

template<int CBF16>
__global__ __launch_bounds__(256, 2)
void bgemm_t(const bf16* __restrict__ A, const bf16* __restrict__ A2, int bnSplit,
             int lda,
             const bf16* __restrict__ W, int ldw,
             const float* __restrict__ bias,
             const float* __restrict__ xres,
             void* __restrict__ Cv, int ldc,
             int K, int doRelu)
{
    extern __shared__ __align__(16) bf16 gsm[];
    bf16* AsB = gsm;                    // 4 stages
    bf16* BsB = gsm + 4 * GEMM_STAGE;   // 4 stages

    int tid  = threadIdx.x;
    int lane = tid & 31;
    int warp = tid >> 5;
    int wm = warp & 1;
    int wn = warp >> 1;
    int bm = blockIdx.y, bn = blockIdx.x;
    int r  = lane >> 2;
    int cc = lane & 3;

    const bf16* Abase = (bn >= bnSplit) ? A2 : A;

    int srow = tid & 127;
    int soff = (tid >> 7) * 16;
    const bf16* Ap = Abase + (size_t)(bm * 128 + srow) * lda + soff;
    const bf16* Wp = W + (size_t)(bn * 128 + srow) * ldw + soff;

    int a_row = wm * 64 + (lane & 15);
    int a_col = ((lane >> 4) & 1) * 8;
    int b_row = wn * 32 + (lane >> 4) * 8 + (lane & 7);
    int b_col = ((lane >> 3) & 1) * 8;

    float acc[4][4][4];
    #pragma unroll
    for (int i = 0; i < 4; i++)
        #pragma unroll
        for (int j = 0; j < 4; j++)
            #pragma unroll
            for (int q = 0; q < 4; q++) acc[i][j][q] = 0.f;

    int niter = K >> 5;
    // prologue: stages 0..2 (guarded; commit count fixed at 3)
    #pragma unroll
    for (int s = 0; s < 3; s++) {
        if (s < niter) {
            bf16* as = AsB + s * GEMM_STAGE;
            bf16* bs = BsB + s * GEMM_STAGE;
            cp16(as + srow * GSTR + soff,     Ap + s * 32);
            cp16(as + srow * GSTR + soff + 8, Ap + s * 32 + 8);
            cp16(bs + srow * GSTR + soff,     Wp + s * 32);
            cp16(bs + srow * GSTR + soff + 8, Wp + s * 32 + 8);
        }
        CP_COMMIT();
    }

    for (int it = 0; it < niter; it++) {
        CP_WAIT2();            // stage `it` complete (<=2 groups pending)
        __syncthreads();       // single barrier: also orders buffer reuse
        if (it + 3 < niter) {
            int s = (it + 3) & 3;
            bf16* as = AsB + s * GEMM_STAGE;
            bf16* bs = BsB + s * GEMM_STAGE;
            const bf16* An = Ap + (it + 3) * 32;
            const bf16* Wn = Wp + (it + 3) * 32;
            cp16(as + srow * GSTR + soff,     An);
            cp16(as + srow * GSTR + soff + 8, An + 8);
            cp16(bs + srow * GSTR + soff,     Wn);
            cp16(bs + srow * GSTR + soff + 8, Wn + 8);
        }
        CP_COMMIT();

        const bf16* Ac = AsB + (it & 3) * GEMM_STAGE;
        const bf16* Bc = BsB + (it & 3) * GEMM_STAGE;
        #pragma unroll
        for (int kb = 0; kb < 2; kb++) {
            uint32_t af[4][4];
            uint32_t bfr[4][2];
            #pragma unroll
            for (int mt = 0; mt < 4; mt++)
                ldsm_x4b(af[mt], Ac + (a_row + mt * 16) * GSTR + kb * 16 + a_col);
            #pragma unroll
            for (int np = 0; np < 2; np++) {
                uint32_t t4[4];
                ldsm_x4b(t4, Bc + (b_row + np * 16) * GSTR + kb * 16 + b_col);
                bfr[2 * np][0]     = t4[0];
                bfr[2 * np][1]     = t4[1];
                bfr[2 * np + 1][0] = t4[2];
                bfr[2 * np + 1][1] = t4[3];
            }
            #pragma unroll
            for (int mt = 0; mt < 4; mt++)
                #pragma unroll
                for (int nt = 0; nt < 4; nt++)
                    mma_bf16(acc[mt][nt], af[mt], bfr[nt]);
        }
        // no tail sync: the next iteration's top __syncthreads provides the
        // write-after-read guarantee for stage reuse.
    }

    int c2 = cc * 2;
    #pragma unroll
    for (int mt = 0; mt < 4; mt++) {
        int row0 = bm * 128 + wm * 64 + mt * 16 + r;
        #pragma unroll
        for (int nt = 0; nt < 4; nt++) {
            int col = bn * 128 + wn * 32 + nt * 8 + c2;
            float bx = bias[col], by = bias[col + 1];
            float2 v0, v1;
            v0.x = acc[mt][nt][0] + bx; v0.y = acc[mt][nt][1] + by;
            v1.x = acc[mt][nt][2] + bx; v1.y = acc[mt][nt][3] + by;
            if (doRelu) {
                v0.x = fmaxf(v0.x, 0.f); v0.y = fmaxf(v0.y, 0.f);
                v1.x = fmaxf(v1.x, 0.f); v1.y = fmaxf(v1.y, 0.f);
            }
            if (xres) {
                float2 x0 = *(const float2*)(xres + (size_t)row0 * ldc + col);
                float2 x1 = *(const float2*)(xres + (size_t)(row0 + 8) * ldc + col);
                v0.x += x0.x; v0.y += x0.y;
                v1.x += x1.x; v1.y += x1.y;
            }
            if (CBF16) {
                bf16* Cp = (bf16*)Cv;
                *(bf162*)(Cp + (size_t)row0 * ldc + col)       = __float22bfloat162_rn(v0);
                *(bf162*)(Cp + (size_t)(row0 + 8) * ldc + col) = __float22bfloat162_rn(v1);
            } else {
                float* Cp = (float*)Cv;
                *(float2*)(Cp + (size_t)row0 * ldc + col)       = v0;
                *(float2*)(Cp + (size_t)(row0 + 8) * ldc + col) = v1;
            }
        }
    }
}

#define KSB  40
#define VST  392
#define ATT_SMEM_BYTES ((S_LEN * KSB + DH * VST) * (int)sizeof(bf16))

__global__ __launch_bounds__(128, 4)
void attn_bf16_kernel(const bf16* __restrict__ qkv, bf16* __restrict__ att)
{
    extern __shared__ __align__(16) bf16 smb[];
    bf16* Ks = smb;
    bf16* Vs = smb + S_LEN * KSB;

    int tid  = threadIdx.x;
    int lane = tid & 31, warp = tid >> 5;
    int r = lane >> 2, cc = lane & 3;
    int seq = blockIdx.x, h = blockIdx.y;
    const bf16* base = qkv + (size_t)seq * S_LEN * 768;

    int brow = (lane & 7) + ((lane >> 4) & 1) * 8;
    int bcol = ((lane >> 3) & 1) * 8;

    #pragma unroll
    for (int i = 0; i < 6; i++) {
        int lin = i * 128 + tid;
        int key = lin >> 1;
        int ch  = (lin & 1) * 16;
        const bf16* src = base + (size_t)key * 768 + 256 + h * DH + ch;
        uint4 k0 = *(const uint4*)src;
        uint4 k1 = *(const uint4*)(src + 8);
        *(uint4*)&Ks[key * KSB + ch]     = k0;
        *(uint4*)&Ks[key * KSB + ch + 8] = k1;
    }
    #pragma unroll
    for (int i = 0; i < 6; i++) {
        int kp  = tid & 31;
        int oct = tid >> 5;
        int keyb = i * 64 + 2 * kp;
        const bf16* v0 = base + (size_t)keyb * 768 + 512 + h * DH + oct * 8;
        uint4 ra = *(const uint4*)v0;
        uint4 rb = *(const uint4*)(v0 + 768);
        const bf16* va = (const bf16*)&ra;
        const bf16* vb = (const bf16*)&rb;
        #pragma unroll
        for (int d = 0; d < 8; d++) {
            bf162 pr;
            pr.x = va[d]; pr.y = vb[d];
            *(bf162*)&Vs[(oct * 8 + d) * VST + keyb] = pr;
        }
    }
    __syncthreads();

    for (int qc = 0; qc < 3; qc++) {
        int qbase = qc * 128 + warp * 32;

        uint32_t qa[2][2][4];
        #pragma unroll
        for (int mt = 0; mt < 2; mt++) {
            const bf16* q0 = base + (size_t)(qbase + mt * 16 + r) * 768 + h * DH;
            const bf16* q1 = q0 + 8 * 768;
            const float sc = 0.2550557815f;   // (1/sqrt(32)) * log2(e)
            #pragma unroll
            for (int kb = 0; kb < 2; kb++) {
                bf162 p00 = *(const bf162*)(q0 + kb * 16 + 2 * cc);
                bf162 p01 = *(const bf162*)(q0 + kb * 16 + 2 * cc + 8);
                bf162 p10 = *(const bf162*)(q1 + kb * 16 + 2 * cc);
                bf162 p11 = *(const bf162*)(q1 + kb * 16 + 2 * cc + 8);
                float2 f;
                f = __bfloat1622float2(p00); qa[mt][kb][0] = packbf(f.x * sc, f.y * sc);
                f = __bfloat1622float2(p10); qa[mt][kb][1] = packbf(f.x * sc, f.y * sc);
                f = __bfloat1622float2(p01); qa[mt][kb][2] = packbf(f.x * sc, f.y * sc);
                f = __bfloat1622float2(p11); qa[mt][kb][3] = packbf(f.x * sc, f.y * sc);
            }
        }

        float lrun[2][2], oacc[2][4][4];
        #pragma unroll
        for (int mt = 0; mt < 2; mt++) {
            lrun[mt][0] = 0.f; lrun[mt][1] = 0.f;
            #pragma unroll
            for (int nt = 0; nt < 4; nt++)
                #pragma unroll
                for (int q = 0; q < 4; q++) oacc[mt][nt][q] = 0.f;
        }

        for (int kt = 0; kt < 12; kt++) {
            int kt32 = kt * 32;

            float sacc[2][4][4];
            #pragma unroll
            for (int mt = 0; mt < 2; mt++)
                #pragma unroll
                for (int nt = 0; nt < 4; nt++)
                    #pragma unroll
                    for (int q = 0; q < 4; q++) sacc[mt][nt][q] = 0.f;

            #pragma unroll
            for (int kb = 0; kb < 2; kb++) {
                #pragma unroll
                for (int kq = 0; kq < 2; kq++) {
                    uint32_t t4[4];
                    ldsm_x4b(t4, Ks + (kt32 + kq * 16 + brow) * KSB + kb * 16 + bcol);
                    #pragma unroll
                    for (int mt = 0; mt < 2; mt++) {
                        mma_bf16(sacc[mt][2 * kq],     qa[mt][kb], t4);
                        mma_bf16(sacc[mt][2 * kq + 1], qa[mt][kb], t4 + 2);
                    }
                }
            }

            #pragma unroll
            for (int kg = 0; kg < 2; kg++) {
                uint32_t bv[4][2];
                #pragma unroll
                for (int np = 0; np < 2; np++) {
                    uint32_t t4[4];
                    ldsm_x4b(t4, Vs + (np * 16 + brow) * VST + kt32 + kg * 16 + bcol);
                    bv[2 * np][0]     = t4[0];
                    bv[2 * np][1]     = t4[1];
                    bv[2 * np + 1][0] = t4[2];
                    bv[2 * np + 1][1] = t4[3];
                }
                #pragma unroll
                for (int mt = 0; mt < 2; mt++) {
                    float e0 = ex2f(sacc[mt][2 * kg][0]);
                    float e1 = ex2f(sacc[mt][2 * kg][1]);
                    float e2 = ex2f(sacc[mt][2 * kg][2]);
                    float e3 = ex2f(sacc[mt][2 * kg][3]);
                    float e4 = ex2f(sacc[mt][2 * kg + 1][0]);
                    float e5 = ex2f(sacc[mt][2 * kg + 1][1]);
                    float e6 = ex2f(sacc[mt][2 * kg + 1][2]);
                    float e7 = ex2f(sacc[mt][2 * kg + 1][3]);
                    lrun[mt][0] += e0 + e1 + e4 + e5;
                    lrun[mt][1] += e2 + e3 + e6 + e7;
                    uint32_t af[4];
                    af[0] = packbf(e0, e1);
                    af[1] = packbf(e2, e3);
                    af[2] = packbf(e4, e5);
                    af[3] = packbf(e6, e7);
                    #pragma unroll
                    for (int nt = 0; nt < 4; nt++)
                        mma_bf16(oacc[mt][nt], af, bv[nt]);
                }
            }
        }

        #pragma unroll
        for (int mt = 0; mt < 2; mt++) {
            float l0 = lrun[mt][0];
            l0 += __shfl_xor_sync(0xFFFFFFFFu, l0, 1);
            l0 += __shfl_xor_sync(0xFFFFFFFFu, l0, 2);
            float l1 = lrun[mt][1];
            l1 += __shfl_xor_sync(0xFFFFFFFFu, l1, 1);
            l1 += __shfl_xor_sync(0xFFFFFFFFu, l1, 2);
            float inv0 = 1.f / l0, inv1 = 1.f / l1;
            size_t grow = (size_t)seq * S_LEN + qbase + mt * 16 + r;
            #pragma unroll
            for (int nt = 0; nt < 4; nt++) {
                int col = h * DH + nt * 8 + 2 * cc;
                float2 v0, v1;
                v0.x = oacc[mt][nt][0] * inv0; v0.y = oacc[mt][nt][1] * inv0;
                v1.x = oacc[mt][nt][2] * inv1; v1.y = oacc[mt][nt][3] * inv1;
                *(bf162*)(att + grow * C_DIM + col)       = __float22bfloat162_rn(v0);
                *(bf162*)(att + (grow + 8) * C_DIM + col) = __float22bfloat162_rn(v1);
            }
        }
    }
}

__global__ void ln_kernel(const float* __restrict__ vin,
                          const float* __restrict__ g, const float* __restrict__ b,
                          float* __restrict__ out, bf16* __restrict__ outh)
{
    int tx = threadIdx.x, ty = threadIdx.y;
    int row = blockIdx.x * 4 + ty;
    size_t base = (size_t)row * C_DIM + tx * 4;
    float4 v = *(const float4*)(vin + base);
    float s  = v.x + v.y + v.z + v.w;
    float s2 = v.x * v.x + v.y * v.y + v.z * v.z + v.w * v.w;
    #pragma unroll
    for (int off = 16; off; off >>= 1) {
        s  += __shfl_xor_sync(0xFFFFFFFFu, s,  off);
        s2 += __shfl_xor_sync(0xFFFFFFFFu, s2, off);
    }
    __shared__ float red[4][2][2];
    int wh = tx >> 5;
    if ((tx & 31) == 0) { red[ty][wh][0] = s; red[ty][wh][1] = s2; }
    __syncthreads();
    float ts  = red[ty][0][0] + red[ty][1][0];
    float ts2 = red[ty][0][1] + red[ty][1][1];
    float mean = ts * (1.f / C_DIM);
    float var  = ts2 * (1.f / C_DIM) - mean * mean;
    float rstd = rsqrtf(var + EPS);
    float4 gv = *(const float4*)(g + tx * 4);
    float4 bv = *(const float4*)(b + tx * 4);
    float4 o;
    o.x = (v.x - mean) * rstd * gv.x + bv.x;
    o.y = (v.y - mean) * rstd * gv.y + bv.y;
    o.z = (v.z - mean) * rstd * gv.z + bv.z;
    o.w = (v.w - mean) * rstd * gv.w + bv.w;
    *(float4*)(out + base) = o;
    bf162 h0 = __floats2bfloat162_rn(o.x, o.y);
    bf162 h1 = __floats2bfloat162_rn(o.z, o.w);
    uint2 pk;
    pk.x = *(uint32_t*)&h0;
    pk.y = *(uint32_t*)&h1;
    *(uint2*)(outh + base) = pk;
}

__global__ void final_out_kernel(const float* __restrict__ x, float* __restrict__ out)
{
    __shared__ float tile[32][33];
    int t0 = blockIdx.x * 32, c0 = blockIdx.y * 32, b = blockIdx.z;
    int tx = threadIdx.x, ty = threadIdx.y;
    #pragma unroll
    for (int i = ty; i < 32; i += 8) {
        int t = t0 + i;
        size_t row = (size_t)(b * NW + (t >> 7)) * S_LEN + CHUNK + (t & 127);
        tile[i][tx] = x[row * C_DIM + c0 + tx];
    }
    __syncthreads();
    #pragma unroll
    for (int i = ty; i < 32; i += 8)
        out[((size_t)b * C_DIM + c0 + i) * T_LEN + t0 + tx] = tile[tx][i];
}

extern "C" void kernel_launch(void* const* d_in, const int* in_sizes, int n_in,
                              void* d_out, int out_size)
{
    (void)in_sizes; (void)n_in; (void)out_size;
    const float* mem   = (const float*)d_in[0];
    const float* sa_w  = (const float*)d_in[1];
    const float* sa_b  = (const float*)d_in[2];
    const float* sa_ow = (const float*)d_in[3];
    const float* sa_ob = (const float*)d_in[4];
    const float* ca_w  = (const float*)d_in[5];
    const float* ca_b  = (const float*)d_in[6];
    const float* ca_ow = (const float*)d_in[7];
    const float* ca_ob = (const float*)d_in[8];
    const float* w1    = (const float*)d_in[9];
    const float* b1f   = (const float*)d_in[10];
    const float* w2    = (const float*)d_in[11];
    const float* b2f   = (const float*)d_in[12];
    const float* ln_g  = (const float*)d_in[13];
    const float* ln_b  = (const float*)d_in[14];

    float *bufA, *bufB, *proj;
    bf16 *bufAh, *bufBh, *qkv, *att, *h, *wbf;
    cudaGetSymbolAddress((void**)&bufA,  g_bufA);
    cudaGetSymbolAddress((void**)&bufB,  g_bufB);
    cudaGetSymbolAddress((void**)&proj,  g_proj);
    cudaGetSymbolAddress((void**)&bufAh, g_bufAh);
    cudaGetSymbolAddress((void**)&bufBh, g_bufBh);
    cudaGetSymbolAddress((void**)&qkv,   g_qkv);
    cudaGetSymbolAddress((void**)&att,   g_att);
    cudaGetSymbolAddress((void**)&h,     g_h);
    cudaGetSymbolAddress((void**)&wbf,   g_wbf);

    cudaFuncSetAttribute(attn_bf16_kernel, cudaFuncAttributeMaxDynamicSharedMemorySize,
                         ATT_SMEM_BYTES);
    cudaFuncSetAttribute(bgemm_t<0>, cudaFuncAttributeMaxDynamicSharedMemorySize,
                         GEMM_SMEM_BYTES);
    cudaFuncSetAttribute(bgemm_t<1>, cudaFuncAttributeMaxDynamicSharedMemorySize,
                         GEMM_SMEM_BYTES);

    const int MB = M_TOTAL / 128;
    dim3 attn_grid(NSEQ, NHEADS);
    const int BIG = 1 << 20;

    float* LI = bufA;   bf16* LIh = bufAh;
    float* OT = bufB;   bf16* OTh = bufBh;

    convert_w_kernel<<< 384, 256>>>(sa_w, wbf + OFF_SAW, 98304);
    convert_w2_kernel<<<dim3(384, 2), 256>>>(sa_ow, wbf + OFF_SAOW, 32768,
                                             ca_w,  wbf + OFF_CAW,  98304);
    build_x_kernel<<<dim3(12, 8, NSEQ), dim3(32, 8)>>>(mem, bufA, bufAh);

    for (int l = 0; l < NLAYERS; l++) {
        const bf16* w_qkv  = wbf + OFF_SAW  + (size_t)l * 196608;
        const bf16* w_saow = wbf + OFF_SAOW + (size_t)l * 65536;
        const bf16* w_caw  = wbf + OFF_CAW  + (size_t)l * 196608;
        const bf16* w_caow = wbf + OFF_CAOW + (size_t)l * 65536;
        const bf16* w_ff1  = wbf + OFF_W1   + (size_t)l * 262144;
        const bf16* w_ff2  = wbf + OFF_W2   + (size_t)l * 262144;

        bgemm_t<1><<<dim3(768/128, MB), 256, GEMM_SMEM_BYTES>>>(
            LIh, LIh, BIG, C_DIM, w_qkv, C_DIM,
            sa_b + (size_t)l*768, nullptr, qkv, 768, C_DIM, 0);
        attn_bf16_kernel<<<attn_grid, 128, ATT_SMEM_BYTES>>>(qkv, att);

        if (l == 0) {
            convert_w2_kernel<<<dim3(512, 2), 256>>>(ca_ow, wbf + OFF_CAOW, 32768,
                                                     w1,    wbf + OFF_W1,  131072);
            convert_w_kernel<<< 512, 256>>>(w2, wbf + OFF_W2, 131072);
        }

        bgemm_t<0><<<dim3(256/128, MB), 256, GEMM_SMEM_BYTES>>>(
            att, att, BIG, C_DIM, w_saow, C_DIM,
            sa_ob + (size_t)l*256, LI, proj, 256, C_DIM, 0);
        ln_kernel<<<M_TOTAL/4, dim3(64, 4)>>>(proj,
                                              ln_g + (size_t)(l*3 + 0)*C_DIM,
                                              ln_b + (size_t)(l*3 + 0)*C_DIM, OT, OTh);

        bgemm_t<1><<<dim3(768/128, MB), 256, GEMM_SMEM_BYTES>>>(
            OTh, LIh, 2, C_DIM, w_caw, C_DIM,
            ca_b + (size_t)l*768, nullptr, qkv, 768, C_DIM, 0);
        attn_bf16_kernel<<<attn_grid, 128, ATT_SMEM_BYTES>>>(qkv, att);
        bgemm_t<0><<<dim3(256/128, MB), 256, GEMM_SMEM_BYTES>>>(
            att, att, BIG, C_DIM, w_caow, C_DIM,
            ca_ob + (size_t)l*256, OT, proj, 256, C_DIM, 0);
        ln_kernel<<<M_TOTAL/4, dim3(64, 4)>>>(proj,
                                              ln_g + (size_t)(l*3 + 1)*C_DIM,
                                              ln_b + (size_t)(l*3 + 1)*C_DIM, LI, LIh);

        bgemm_t<1><<<dim3(FF_DIM/128, MB), 256, GEMM_SMEM_BYTES>>>(
            LIh, LIh, BIG, C_DIM, w_ff1, C_DIM,
            b1f + (size_t)l*FF_DIM, nullptr, h, FF_DIM, C_DIM, 1);
        bgemm_t<0><<<dim3(256/128, MB), 256, GEMM_SMEM_BYTES>>>(
            h, h, BIG, FF_DIM, w_ff2, FF_DIM,
            b2f + (size_t)l*256, LI, proj, 256, FF_DIM, 0);
        ln_kernel<<<M_TOTAL/4, dim3(64, 4)>>>(proj,
                                              ln_g + (size_t)(l*3 + 2)*C_DIM,
                                              ln_b + (size_t)(l*3 + 2)*C_DIM, OT, OTh);

        float* t0 = LI; LI = OT; OT = t0;
        bf16*  t1 = LIh; LIh = OTh; OTh = t1;
    }

    final_out_kernel<<<dim3(128, 8, 4), dim3(32, 8)>>>(LI, (float*)d_out);
}